// round 14
// baseline (speedup 1.0000x reference)
#include <cuda_runtime.h>
#include <cuda_bf16.h>
#include <cstdint>
#include <cstddef>

// Problem dims (fixed by the dataset)
#define B_ 8
#define E_ 1024
#define D_ 1024
#define F_ 768
#define H_ 1024
#define M_ 8192   // B*E == B*D rows

// GEMM tiling (fp8, f32 accum): R6/R12 config (best measured in-graph)
#define BM 128
#define BN 128
#define BK 64
#define KITERS (F_ / BK)   // 12
#define NB 3
#define NT 8               // n-tiles (H/BN)
#define WSCALE 16.0f       // W pre-scale into e4m3 normal range
#define WINV   0.0625f

// smem: per buffer A 128x80B + B 128x80B
#define ROWW   20                         // words per row (64B data + 16B pad)
#define ATILE  (BM*ROWW*4)                // 10240 B
#define BUFSZ  (2*ATILE)                  // 20480 B (A + B)
#define SM_EXTRA (NB*BUFSZ)               // 61440
#define OF_W1  (SM_EXTRA)                 // 3*128 floats
#define OF_BS  (OF_W1 + 3*BN*4)
#define OF_PPS (OF_BS + BN*4)
#define SM_TOTAL (OF_PPS + BM*2*3*4)      // ~65 KB -> 2 CTAs/SM

#define NLAB (B_*D_*E_)                   // 8388608 labels
#define NLBLK 512                         // label-packing blocks inside gemm launch
#define LPB (NLAB / NLBLK)                // 16384 labels per block

// ---------------- scratch (static device globals; no allocs) ----------------
__device__ uint8_t g_xe[(size_t)M_ * F_];    // e4m3
__device__ uint8_t g_xd[(size_t)M_ * F_];
__device__ uint8_t g_we[(size_t)H_ * F_];    // e4m3, scaled x16
__device__ uint8_t g_wd[(size_t)H_ * F_];
__device__ uint8_t g_lab8[NLAB];             // packed int8 labels
__device__ float4 g_pp[(size_t)2 * M_ * NT]; // per-(row, ntile) proj partials
__device__ float4 g_ep[M_];                  // e_proj * log2e (masked)
__device__ float4 g_dp[M_];                  // (d_proj*mask + b1) * log2e
__device__ double g_sum;
__device__ unsigned long long g_cnt;
__device__ int g_is32;                       // label dtype: 1 = int32, 0 = int64
__device__ int g_done;                       // last-block flag for fused final
__device__ int g_tc[2*64];                   // per-(z, mtile) completion counters

// ---------------- helpers ----------------
__device__ __forceinline__ float ex2f(float x){ float r; asm("ex2.approx.f32 %0, %1;" : "=f"(r) : "f"(x)); return r; }
__device__ __forceinline__ float lg2f(float x){ float r; asm("lg2.approx.f32 %0, %1;" : "=f"(r) : "f"(x)); return r; }

__device__ __forceinline__ void mma_fp8(float c[4], const uint32_t a[4], const uint32_t b[2]){
  asm volatile(
    "mma.sync.aligned.m16n8k32.row.col.f32.e4m3.e4m3.f32 "
    "{%0,%1,%2,%3}, {%4,%5,%6,%7}, {%8,%9}, {%0,%1,%2,%3};\n"
    : "+f"(c[0]), "+f"(c[1]), "+f"(c[2]), "+f"(c[3])
    : "r"(a[0]), "r"(a[1]), "r"(a[2]), "r"(a[3]), "r"(b[0]), "r"(b[1]));
}

__device__ __forceinline__ void ldsm4(uint32_t r[4], uint32_t addr){
  asm volatile("ldmatrix.sync.aligned.m8n8.x4.shared.b16 {%0,%1,%2,%3}, [%4];"
    : "=r"(r[0]), "=r"(r[1]), "=r"(r[2]), "=r"(r[3]) : "r"(addr));
}

__device__ __forceinline__ void cp16(uint32_t smem_dst, const void* gsrc){
  asm volatile("cp.async.cg.shared.global [%0], [%1], 16;\n" :: "r"(smem_dst), "l"(gsrc));
}

// pack 4 fp32 -> 4 e4m3 bytes, round-to-nearest
__device__ __forceinline__ uint32_t pack4_e4m3(float4 v, float s){
  uint16_t lo, hi;
  asm("cvt.rn.satfinite.e4m3x2.f32 %0, %1, %2;" : "=h"(lo) : "f"(v.y * s), "f"(v.x * s));
  asm("cvt.rn.satfinite.e4m3x2.f32 %0, %1, %2;" : "=h"(hi) : "f"(v.w * s), "f"(v.z * s));
  return (uint32_t)lo | ((uint32_t)hi << 16);
}

// ---------------- launch 1: all conversions + init (exact R12 version) ----------------
#define NX4 ((M_ * F_) / 4)   // 1572864
#define NW4 ((H_ * F_) / 4)   // 196608
__global__ __launch_bounds__(256) void cvt_all_kernel(
    const float4* __restrict__ enc, const float4* __restrict__ dec,
    const float4* __restrict__ We,  const float4* __restrict__ Wd,
    const int* __restrict__ labw)
{
  int i = blockIdx.x * 256 + threadIdx.x;
  if (i < NX4){
    ((uint32_t*)g_xe)[i] = pack4_e4m3(enc[i], 1.0f);
    ((uint32_t*)g_xd)[i] = pack4_e4m3(dec[i], 1.0f);
  }
  if (i < NW4){
    ((uint32_t*)g_we)[i] = pack4_e4m3(We[i], WSCALE);
    ((uint32_t*)g_wd)[i] = pack4_e4m3(Wd[i], WSCALE);
  }
  if (blockIdx.x == 0){
    __shared__ int flag;
    if (threadIdx.x == 0) flag = 0;
    __syncthreads();
    // int64 labels: odd words are 0/-1; int32: odd words are labels (1/2 appear)
    for (int j = threadIdx.x; j < 4096; j += 256){
      int v = labw[2*j + 1];
      if (v == 1 || v == 2) flag = 1;
    }
    if (threadIdx.x < 128) g_tc[threadIdx.x] = 0;
    __syncthreads();
    if (threadIdx.x == 0){
      g_is32 = flag;
      g_sum = 0.0;
      g_cnt = 0ull;
      g_done = 0;
    }
  }
}

// ---------------- launch 2: fused GEMM + proj + combine, with interleaved label packing ----------------
// Flat grid of 1536 blocks: bid%3==2 -> label-pack block (512); else gemm block (1024).
__global__ void __launch_bounds__(256, 2) gemm_kernel(
    const float* __restrict__ be, const float* __restrict__ bd,
    const float* __restrict__ W1,
    const float* __restrict__ emask, const float* __restrict__ dmask,
    const float* __restrict__ b1,
    const int* __restrict__ labw)
{
  const int bid = blockIdx.x;
  const int tid = threadIdx.x;

  // ---- label-packing role: int64/int32 labels -> int8 ----
  if ((bid % 3) == 2){
    const int lidx = bid / 3;                 // 0..511
    const int base = lidx * LPB;              // label index base
    const int is32 = g_is32;
    const int4* __restrict__ src = (const int4*)labw;
    uint32_t* __restrict__ dstw = (uint32_t*)(g_lab8 + base);
    #pragma unroll 4
    for (int it = 0; it < 16; it++){
      int li = base + (it*256 + tid)*4;       // 4 labels per step
      uint32_t o;
      if (is32){
        int4 v = src[li >> 2];
        o = (uint32_t)(v.x & 0xff) | ((uint32_t)(v.y & 0xff) << 8) |
            ((uint32_t)(v.z & 0xff) << 16) | ((uint32_t)(v.w & 0xff) << 24);
      } else {
        int4 v0 = src[li >> 1];               // labels li, li+1 (low words .x, .z)
        int4 v1 = src[(li >> 1) + 1];         // labels li+2, li+3
        o = (uint32_t)(v0.x & 0xff) | ((uint32_t)(v0.z & 0xff) << 8) |
            ((uint32_t)(v1.x & 0xff) << 16) | ((uint32_t)(v1.z & 0xff) << 24);
      }
      dstw[(it*256 + tid)] = o;
    }
    return;
  }

  // ---- gemm role ----
  const int gidx  = (bid / 3) * 2 + (bid % 3);  // 0..1023
  const int mtile = gidx & 63;
  const int ntile = (gidx >> 6) & 7;
  const int z     = gidx >> 9;

  extern __shared__ char sraw[];
  float* w1s = (float*)(sraw + OF_W1);   // [3][BN]
  float* bs  = (float*)(sraw + OF_BS);   // [BN]
  float* pps = (float*)(sraw + OF_PPS);  // [BM][2][3]
  const uint32_t sbase = (uint32_t)__cvta_generic_to_shared(sraw);

  const uint8_t* __restrict__ X = z ? g_xd : g_xe;
  const uint8_t* __restrict__ W = z ? g_wd : g_we;
  const int m0 = mtile * BM;
  const int n0 = ntile * BN;

  const int wid  = tid >> 5, lane = tid & 31;
  const int g    = lane >> 2, tg = lane & 3;
  const int wm   = (wid >> 1) * 32;   // 4 warps in m (32 rows each)
  const int wn   = (wid & 1)  * 64;   // 2 warps in n (64 cols each)

  // ldmatrix per-lane address bases (80B row stride)
  const int q  = lane >> 3, r8 = lane & 7;
  const int rowA = wm + (q & 1) * 8 + r8;        // + mt*16
  const int wA   = (q >> 1) * 4;                 // + kb
  const int rowB0 = wn + (q >> 1) * 8 + r8;      // + np*16
  const int wB   = (q & 1) * 4;                  // + kb

  float c[2][8][4];
  #pragma unroll
  for (int mt = 0; mt < 2; mt++)
    #pragma unroll
    for (int nt = 0; nt < 8; nt++)
      #pragma unroll
      for (int k = 0; k < 4; k++) c[mt][nt][k] = 0.f;

  // epilogue constants into smem up front (protected by first loop sync)
  if (tid < BN) bs[tid] = (z ? bd : be)[n0 + tid];
  const int off1 = z ? 0 : H_;
  for (int i = tid; i < 3*BN; i += 256)
    w1s[i] = W1[(i >> 7) * (2*H_) + off1 + n0 + (i & 127)];

  // ---- async tile loader: 2 cp16 for A, 2 for B per thread ----
  auto load_tiles = [&](int s, int k0){
    #pragma unroll
    for (int i = 0; i < 2; i++){            // A: 512 16B-chunks
      int r  = (tid + 256*i) >> 2, ck = (tid + 256*i) & 3;
      uint32_t dst = sbase + (uint32_t)(s*BUFSZ + (r*ROWW + ck*4) * 4);
      cp16(dst, X + (size_t)(m0 + r)*F_ + k0 + ck*16);
    }
    #pragma unroll
    for (int i = 0; i < 2; i++){            // B: 512 16B-chunks
      int r  = (tid + 256*i) >> 2, ck = (tid + 256*i) & 3;
      uint32_t dst = sbase + (uint32_t)(s*BUFSZ + ATILE + (r*ROWW + ck*4) * 4);
      cp16(dst, W + (size_t)(n0 + r)*F_ + k0 + ck*16);
    }
  };

  load_tiles(0, 0);  asm volatile("cp.async.commit_group;\n");
  load_tiles(1, BK); asm volatile("cp.async.commit_group;\n");

  int s = 0;
  for (int it = 0; it < KITERS; it++){
    if (it + 1 < KITERS) asm volatile("cp.async.wait_group 1;\n");
    else                 asm volatile("cp.async.wait_group 0;\n");
    __syncthreads();   // single barrier per iter: also frees buffer (it+2)%3

    const uint32_t sA = sbase + s*BUFSZ;
    const uint32_t sB = sA + ATILE;
    #pragma unroll
    for (int ks = 0; ks < 2; ks++){         // two K=32 steps per 64B row
      const int kb = ks * 8;
      uint32_t a[2][4], b[8][2];
      #pragma unroll
      for (int mt = 0; mt < 2; mt++)
        ldsm4(a[mt], sA + (uint32_t)(((rowA + mt*16)*ROWW + kb + wA) * 4));
      #pragma unroll
      for (int np = 0; np < 4; np++){       // nt pairs (2 nt per ldsm4)
        uint32_t bb[4];
        ldsm4(bb, sB + (uint32_t)(((rowB0 + np*16)*ROWW + kb + wB) * 4));
        b[np*2    ][0] = bb[0]; b[np*2    ][1] = bb[1];
        b[np*2 + 1][0] = bb[2]; b[np*2 + 1][1] = bb[3];
      }
      #pragma unroll
      for (int mt = 0; mt < 2; mt++)
        #pragma unroll
        for (int nt = 0; nt < 8; nt++)
          mma_fp8(c[mt][nt], a[mt], b[nt]);
    }

    if (it + 2 < KITERS){
      load_tiles((it + 2) % NB, (it + 2) * BK);
      asm volatile("cp.async.commit_group;\n");
    }
    s = (s + 1 == NB) ? 0 : s + 1;
  }
  __syncthreads();

  // ---- fused epilogue: unscale + bias + relu + 3-class projection partials ----
  float part[2][2][3];
  #pragma unroll
  for (int mt = 0; mt < 2; mt++)
    #pragma unroll
    for (int sb = 0; sb < 2; sb++)
      #pragma unroll
      for (int cl = 0; cl < 3; cl++) part[mt][sb][cl] = 0.f;

  #pragma unroll
  for (int nt = 0; nt < 8; nt++){
    int col = wn + nt*8 + tg*2;
    float bv0 = bs[col], bv1 = bs[col + 1];
    float w[3][2];
    #pragma unroll
    for (int cl = 0; cl < 3; cl++){ w[cl][0] = w1s[cl*BN + col]; w[cl][1] = w1s[cl*BN + col + 1]; }
    #pragma unroll
    for (int mt = 0; mt < 2; mt++){
      float h00 = fmaxf(fmaf(c[mt][nt][0], WINV, bv0), 0.f);
      float h01 = fmaxf(fmaf(c[mt][nt][1], WINV, bv1), 0.f);
      float h10 = fmaxf(fmaf(c[mt][nt][2], WINV, bv0), 0.f);
      float h11 = fmaxf(fmaf(c[mt][nt][3], WINV, bv1), 0.f);
      #pragma unroll
      for (int cl = 0; cl < 3; cl++){
        part[mt][0][cl] = fmaf(h00, w[cl][0], fmaf(h01, w[cl][1], part[mt][0][cl]));
        part[mt][1][cl] = fmaf(h10, w[cl][0], fmaf(h11, w[cl][1], part[mt][1][cl]));
      }
    }
  }

  // reduce over the 4 tg-lanes sharing each row
  #pragma unroll
  for (int mt = 0; mt < 2; mt++)
    #pragma unroll
    for (int sb = 0; sb < 2; sb++)
      #pragma unroll
      for (int cl = 0; cl < 3; cl++){
        float v = part[mt][sb][cl];
        v += __shfl_xor_sync(0xffffffffu, v, 1);
        v += __shfl_xor_sync(0xffffffffu, v, 2);
        part[mt][sb][cl] = v;
      }
  if (tg == 0){
    #pragma unroll
    for (int mt = 0; mt < 2; mt++)
      #pragma unroll
      for (int sb = 0; sb < 2; sb++){
        int row = wm + mt*16 + g + sb*8;
        #pragma unroll
        for (int cl = 0; cl < 3; cl++)
          pps[(row*2 + (wid & 1))*3 + cl] = part[mt][sb][cl];
      }
  }
  __syncthreads();
  if (tid < BM){
    float4 o;
    o.x = pps[(tid*2)*3 + 0] + pps[(tid*2+1)*3 + 0];
    o.y = pps[(tid*2)*3 + 1] + pps[(tid*2+1)*3 + 1];
    o.z = pps[(tid*2)*3 + 2] + pps[(tid*2+1)*3 + 2];
    o.w = 0.f;
    g_pp[((size_t)z * M_ + m0 + tid) * NT + ntile] = o;
  }
  __syncthreads();

  // ---- in-kernel combine: last CTA of each (z, mtile) finalizes the 8 partials ----
  __shared__ int lastf;
  if (tid == 0){
    __threadfence();
    int old = atomicAdd(&g_tc[z*64 + mtile], 1);
    lastf = (old == NT - 1);
  }
  __syncthreads();
  if (lastf && tid < BM){
    __threadfence();
    const float4* pp = &g_pp[((size_t)z * M_ + m0 + tid) * NT];
    float s0 = 0.f, s1 = 0.f, s2 = 0.f;
    #pragma unroll
    for (int t = 0; t < NT; t++){ float4 v = pp[t]; s0 += v.x; s1 += v.y; s2 += v.z; }
    const float LOG2E = 1.4426950408889634f;
    int r = m0 + tid;
    if (z == 0){
      float mk = emask[r];
      g_ep[r] = make_float4(mk*s0*LOG2E, mk*s1*LOG2E, mk*s2*LOG2E, 0.f);
    } else {
      float mk = dmask[r];
      g_dp[r] = make_float4((mk*s0 + b1[0])*LOG2E, (mk*s1 + b1[1])*LOG2E, (mk*s2 + b1[2])*LOG2E, 0.f);
    }
  }
}

// ---------------- launch 3: grid NLL on packed int8 labels + fused final ----------------
__global__ __launch_bounds__(256) void grid_kernel(float* __restrict__ out)
{
  __shared__ float4 eps[1024];
  __shared__ float4 dps[16];
  __shared__ float redL[8];
  __shared__ int   redC[8];

  const int tid = threadIdx.x;
  const int b   = blockIdx.x >> 6;
  const int d0  = (blockIdx.x & 63) * 16;

  #pragma unroll
  for (int i = 0; i < 4; i++) eps[tid + 256*i] = g_ep[b*E_ + tid + 256*i];
  if (tid < 16) dps[tid] = g_dp[b*D_ + d0 + tid];
  __syncthreads();

  float accL = 0.f;
  int   accC = 0;
  const int e0 = tid * 4;

  for (int di = 0; di < 16; di++){
    float4 dp = dps[di];
    const uchar4* __restrict__ l4 = (const uchar4*)(g_lab8 + (((size_t)(b*D_ + d0 + di)) << 10));
    uchar4 lv = l4[tid];
    int li[4] = { (int)(signed char)lv.x, (int)(signed char)lv.y,
                  (int)(signed char)lv.z, (int)(signed char)lv.w };
    #pragma unroll
    for (int i = 0; i < 4; i++){
      float4 ep = eps[e0 + i];
      float l0 = dp.x + ep.x;
      float l1 = dp.y + ep.y;
      float l2 = dp.z + ep.z;
      float m12 = fmaxf(l1, l2), n12 = fminf(l1, l2);
      float m   = fmaxf(l0, m12), o1 = fminf(l0, m12);
      float sx = 1.0f + ex2f(o1 - m) + ex2f(n12 - m);
      float L = m + lg2f(sx);
      float ll = (li[i] == 0) ? l0 : ((li[i] == 1) ? l1 : l2);
      if (li[i] >= 0){ accL += L - ll; accC++; }
    }
  }

  #pragma unroll
  for (int o = 16; o; o >>= 1){
    accL += __shfl_xor_sync(0xffffffffu, accL, o);
    accC += __shfl_xor_sync(0xffffffffu, accC, o);
  }
  const int wid = tid >> 5, lane = tid & 31;
  if (lane == 0){ redL[wid] = accL; redC[wid] = accC; }
  __syncthreads();
  if (wid == 0 && lane < 8){
    float v = redL[lane];
    int   ct = redC[lane];
    #pragma unroll
    for (int o = 4; o; o >>= 1){
      v  += __shfl_xor_sync(0x000000ffu, v, o);
      ct += __shfl_xor_sync(0x000000ffu, ct, o);
    }
    if (lane == 0){
      atomicAdd(&g_sum, (double)v);
      atomicAdd(&g_cnt, (unsigned long long)ct);
      __threadfence();
      int done = atomicAdd(&g_done, 1);
      if (done == gridDim.x - 1){
        double denom = g_cnt ? (double)g_cnt : 1.0;
        out[0] = (float)(0.69314718055994530942 * g_sum / denom);
      }
    }
  }
}

// ---------------- launch ----------------
extern "C" void kernel_launch(void* const* d_in, const int* in_sizes, int n_in,
                              void* d_out, int out_size)
{
  (void)in_sizes; (void)n_in; (void)out_size;
  const float* enc   = (const float*)d_in[0];
  const float* dec   = (const float*)d_in[1];   // (1,B,D,F) == (B,D,F)
  const float* emask = (const float*)d_in[2];
  const float* dmask = (const float*)d_in[3];
  const float* W_e   = (const float*)d_in[4];
  const float* b_e   = (const float*)d_in[5];
  const float* W_d   = (const float*)d_in[6];
  const float* b_d   = (const float*)d_in[7];
  const float* W1    = (const float*)d_in[8];
  const float* b1    = (const float*)d_in[9];
  const int*   lab   = (const int*)d_in[10];
  float* out = (float*)d_out;

  static int smem_set = 0;
  if (!smem_set){
    cudaFuncSetAttribute(gemm_kernel, cudaFuncAttributeMaxDynamicSharedMemorySize, SM_TOTAL);
    smem_set = 1;
  }

  // launch 1: conversions + init
  cvt_all_kernel<<<(NX4 + 255)/256, 256>>>((const float4*)enc, (const float4*)dec,
                                           (const float4*)W_e, (const float4*)W_d, lab);

  // launch 2: GEMM + proj + combine, with interleaved label packing (1536 blocks)
  gemm_kernel<<<1536, 256, SM_TOTAL>>>(b_e, b_d, W1, emask, dmask, b1, lab);

  // launch 3: grid NLL + final
  grid_kernel<<<512, 256>>>(out);
}

// round 15
// speedup vs baseline: 1.1550x; 1.1550x over previous
#include <cuda_runtime.h>
#include <cuda_bf16.h>
#include <cstdint>
#include <cstddef>

// Problem dims (fixed by the dataset)
#define B_ 8
#define E_ 1024
#define D_ 1024
#define F_ 768
#define H_ 1024
#define M_ 8192   // B*E == B*D rows

// GEMM tiling (fp8, f32 accum): R6/R12 config (best measured in-graph)
#define BM 128
#define BN 128
#define BK 64
#define KITERS (F_ / BK)   // 12
#define NB 3
#define NT 8               // n-tiles (H/BN)
#define WSCALE 16.0f       // W pre-scale into e4m3 normal range
#define WINV   0.0625f

// smem: per buffer A 128x80B + B 128x80B
#define ROWW   20                         // words per row (64B data + 16B pad)
#define ATILE  (BM*ROWW*4)                // 10240 B
#define BUFSZ  (2*ATILE)                  // 20480 B (A + B)
#define SM_EXTRA (NB*BUFSZ)               // 61440
#define OF_W1  (SM_EXTRA)                 // 3*128 floats
#define OF_BS  (OF_W1 + 3*BN*4)
#define OF_PPS (OF_BS + BN*4)
#define SM_TOTAL (OF_PPS + BM*2*3*4)      // ~65 KB -> 2 CTAs/SM

#define NLAB (B_*D_*E_)                   // 8388608 labels
#define NLBLK 512                         // label-packing blocks appended to cvt launch
#define LPB (NLAB / NLBLK)                // 16384 labels per block

// ---------------- scratch (static device globals; no allocs) ----------------
__device__ uint8_t g_xe[(size_t)M_ * F_];    // e4m3
__device__ uint8_t g_xd[(size_t)M_ * F_];
__device__ uint8_t g_we[(size_t)H_ * F_];    // e4m3, scaled x16
__device__ uint8_t g_wd[(size_t)H_ * F_];
__device__ uint8_t g_lab8[NLAB];             // packed int8 labels
__device__ float4 g_pp[(size_t)2 * M_ * NT]; // per-(row, ntile) proj partials
__device__ float4 g_ep[M_];                  // e_proj * log2e (masked)
__device__ float4 g_dp[M_];                  // (d_proj*mask + b1) * log2e
__device__ double g_sum;
__device__ unsigned long long g_cnt;
__device__ int g_is32;                       // label dtype: 1 = int32, 0 = int64
__device__ int g_done;                       // last-block flag for fused final
__device__ int g_tc[2*64];                   // per-(z, mtile) completion counters

// ---------------- helpers ----------------
__device__ __forceinline__ float ex2f(float x){ float r; asm("ex2.approx.f32 %0, %1;" : "=f"(r) : "f"(x)); return r; }
__device__ __forceinline__ float lg2f(float x){ float r; asm("lg2.approx.f32 %0, %1;" : "=f"(r) : "f"(x)); return r; }

__device__ __forceinline__ void mma_fp8(float c[4], const uint32_t a[4], const uint32_t b[2]){
  asm volatile(
    "mma.sync.aligned.m16n8k32.row.col.f32.e4m3.e4m3.f32 "
    "{%0,%1,%2,%3}, {%4,%5,%6,%7}, {%8,%9}, {%0,%1,%2,%3};\n"
    : "+f"(c[0]), "+f"(c[1]), "+f"(c[2]), "+f"(c[3])
    : "r"(a[0]), "r"(a[1]), "r"(a[2]), "r"(a[3]), "r"(b[0]), "r"(b[1]));
}

__device__ __forceinline__ void ldsm4(uint32_t r[4], uint32_t addr){
  asm volatile("ldmatrix.sync.aligned.m8n8.x4.shared.b16 {%0,%1,%2,%3}, [%4];"
    : "=r"(r[0]), "=r"(r[1]), "=r"(r[2]), "=r"(r[3]) : "r"(addr));
}

__device__ __forceinline__ void cp16(uint32_t smem_dst, const void* gsrc){
  asm volatile("cp.async.cg.shared.global [%0], [%1], 16;\n" :: "r"(smem_dst), "l"(gsrc));
}

// pack 4 fp32 -> 4 e4m3 bytes, round-to-nearest
__device__ __forceinline__ uint32_t pack4_e4m3(float4 v, float s){
  uint16_t lo, hi;
  asm("cvt.rn.satfinite.e4m3x2.f32 %0, %1, %2;" : "=h"(lo) : "f"(v.y * s), "f"(v.x * s));
  asm("cvt.rn.satfinite.e4m3x2.f32 %0, %1, %2;" : "=h"(hi) : "f"(v.w * s), "f"(v.z * s));
  return (uint32_t)lo | ((uint32_t)hi << 16);
}

// ---------------- launch 1: all conversions + init + label packing ----------------
#define NX4 ((M_ * F_) / 4)   // 1572864
#define NW4 ((H_ * F_) / 4)   // 196608
#define XBLKS ((NX4 + 255) / 256)   // 6144 cvt blocks; label blocks appended after
__global__ __launch_bounds__(256) void cvt_all_kernel(
    const float4* __restrict__ enc, const float4* __restrict__ dec,
    const float4* __restrict__ We,  const float4* __restrict__ Wd,
    const int* __restrict__ labw)
{
  const int bx = blockIdx.x;
  const int tid = threadIdx.x;

  // ---- appended label-packing blocks: int64/int32 labels -> int8 ----
  if (bx >= XBLKS){
    const int lidx = bx - XBLKS;              // 0..511
    // local dtype detection (no dependence on g_is32): int32 layout puts labels
    // in odd words; 256 samples of uniform{0,1,2} miss {1,2} w.p. (1/3)^256.
    __shared__ int sflag;
    if (tid == 0) sflag = 0;
    __syncthreads();
    {
      int v = labw[2*tid + 1];
      if (v == 1 || v == 2) sflag = 1;
    }
    __syncthreads();
    const int is32 = sflag;
    const int base = lidx * LPB;
    const int4* __restrict__ src = (const int4*)labw;
    uint32_t* __restrict__ dstw = (uint32_t*)(g_lab8 + base);
    #pragma unroll 4
    for (int it = 0; it < 16; it++){
      int li = base + (it*256 + tid)*4;       // 4 labels per step
      uint32_t o;
      if (is32){
        int4 v = src[li >> 2];
        o = (uint32_t)(v.x & 0xff) | ((uint32_t)(v.y & 0xff) << 8) |
            ((uint32_t)(v.z & 0xff) << 16) | ((uint32_t)(v.w & 0xff) << 24);
      } else {
        int4 v0 = src[li >> 1];               // labels li, li+1 (low words .x, .z)
        int4 v1 = src[(li >> 1) + 1];         // labels li+2, li+3
        o = (uint32_t)(v0.x & 0xff) | ((uint32_t)(v0.z & 0xff) << 8) |
            ((uint32_t)(v1.x & 0xff) << 16) | ((uint32_t)(v1.z & 0xff) << 24);
      }
      dstw[(it*256 + tid)] = o;
    }
    return;
  }

  // ---- conversion blocks (exact R12 behavior) ----
  int i = bx * 256 + tid;
  if (i < NX4){
    ((uint32_t*)g_xe)[i] = pack4_e4m3(enc[i], 1.0f);
    ((uint32_t*)g_xd)[i] = pack4_e4m3(dec[i], 1.0f);
  }
  if (i < NW4){
    ((uint32_t*)g_we)[i] = pack4_e4m3(We[i], WSCALE);
    ((uint32_t*)g_wd)[i] = pack4_e4m3(Wd[i], WSCALE);
  }
  if (bx == 0){
    if (tid < 128) g_tc[tid] = 0;
    if (tid == 0){
      g_sum = 0.0;
      g_cnt = 0ull;
      g_done = 0;
    }
  }
}

// ---------------- launch 2: fused GEMM + 3-class proj + in-kernel combine (exact R12) ----------------
// Grid (64, 8, 2); z=0 enc, z=1 dec. 2 CTAs/SM, 3-stage cp.async pipeline.
__global__ void __launch_bounds__(256, 2) gemm_kernel(
    const float* __restrict__ be, const float* __restrict__ bd,
    const float* __restrict__ W1,
    const float* __restrict__ emask, const float* __restrict__ dmask,
    const float* __restrict__ b1)
{
  extern __shared__ char sraw[];
  float* w1s = (float*)(sraw + OF_W1);   // [3][BN]
  float* bs  = (float*)(sraw + OF_BS);   // [BN]
  float* pps = (float*)(sraw + OF_PPS);  // [BM][2][3]
  const uint32_t sbase = (uint32_t)__cvta_generic_to_shared(sraw);

  const int z  = blockIdx.z;
  const uint8_t* __restrict__ X = z ? g_xd : g_xe;
  const uint8_t* __restrict__ W = z ? g_wd : g_we;
  const int m0 = blockIdx.x * BM;
  const int n0 = blockIdx.y * BN;

  const int tid  = threadIdx.x;
  const int wid  = tid >> 5, lane = tid & 31;
  const int g    = lane >> 2, tg = lane & 3;
  const int wm   = (wid >> 1) * 32;   // 4 warps in m (32 rows each)
  const int wn   = (wid & 1)  * 64;   // 2 warps in n (64 cols each)

  // ldmatrix per-lane address bases (80B row stride)
  const int q  = lane >> 3, r8 = lane & 7;
  const int rowA = wm + (q & 1) * 8 + r8;        // + mt*16
  const int wA   = (q >> 1) * 4;                 // + kb
  const int rowB0 = wn + (q >> 1) * 8 + r8;      // + np*16
  const int wB   = (q & 1) * 4;                  // + kb

  float c[2][8][4];
  #pragma unroll
  for (int mt = 0; mt < 2; mt++)
    #pragma unroll
    for (int nt = 0; nt < 8; nt++)
      #pragma unroll
      for (int k = 0; k < 4; k++) c[mt][nt][k] = 0.f;

  // epilogue constants into smem up front (protected by first loop sync)
  if (tid < BN) bs[tid] = (z ? bd : be)[n0 + tid];
  const int off1 = z ? 0 : H_;
  for (int i = tid; i < 3*BN; i += 256)
    w1s[i] = W1[(i >> 7) * (2*H_) + off1 + n0 + (i & 127)];

  // ---- async tile loader: 2 cp16 for A, 2 for B per thread ----
  auto load_tiles = [&](int s, int k0){
    #pragma unroll
    for (int i = 0; i < 2; i++){            // A: 512 16B-chunks
      int r  = (tid + 256*i) >> 2, ck = (tid + 256*i) & 3;
      uint32_t dst = sbase + (uint32_t)(s*BUFSZ + (r*ROWW + ck*4) * 4);
      cp16(dst, X + (size_t)(m0 + r)*F_ + k0 + ck*16);
    }
    #pragma unroll
    for (int i = 0; i < 2; i++){            // B: 512 16B-chunks
      int r  = (tid + 256*i) >> 2, ck = (tid + 256*i) & 3;
      uint32_t dst = sbase + (uint32_t)(s*BUFSZ + ATILE + (r*ROWW + ck*4) * 4);
      cp16(dst, W + (size_t)(n0 + r)*F_ + k0 + ck*16);
    }
  };

  load_tiles(0, 0);  asm volatile("cp.async.commit_group;\n");
  load_tiles(1, BK); asm volatile("cp.async.commit_group;\n");

  int s = 0;
  for (int it = 0; it < KITERS; it++){
    if (it + 1 < KITERS) asm volatile("cp.async.wait_group 1;\n");
    else                 asm volatile("cp.async.wait_group 0;\n");
    __syncthreads();   // single barrier per iter: also frees buffer (it+2)%3

    const uint32_t sA = sbase + s*BUFSZ;
    const uint32_t sB = sA + ATILE;
    #pragma unroll
    for (int ks = 0; ks < 2; ks++){         // two K=32 steps per 64B row
      const int kb = ks * 8;
      uint32_t a[2][4], b[8][2];
      #pragma unroll
      for (int mt = 0; mt < 2; mt++)
        ldsm4(a[mt], sA + (uint32_t)(((rowA + mt*16)*ROWW + kb + wA) * 4));
      #pragma unroll
      for (int np = 0; np < 4; np++){       // nt pairs (2 nt per ldsm4)
        uint32_t bb[4];
        ldsm4(bb, sB + (uint32_t)(((rowB0 + np*16)*ROWW + kb + wB) * 4));
        b[np*2    ][0] = bb[0]; b[np*2    ][1] = bb[1];
        b[np*2 + 1][0] = bb[2]; b[np*2 + 1][1] = bb[3];
      }
      #pragma unroll
      for (int mt = 0; mt < 2; mt++)
        #pragma unroll
        for (int nt = 0; nt < 8; nt++)
          mma_fp8(c[mt][nt], a[mt], b[nt]);
    }

    if (it + 2 < KITERS){
      load_tiles((it + 2) % NB, (it + 2) * BK);
      asm volatile("cp.async.commit_group;\n");
    }
    s = (s + 1 == NB) ? 0 : s + 1;
  }
  __syncthreads();

  // ---- fused epilogue: unscale + bias + relu + 3-class projection partials ----
  float part[2][2][3];
  #pragma unroll
  for (int mt = 0; mt < 2; mt++)
    #pragma unroll
    for (int sb = 0; sb < 2; sb++)
      #pragma unroll
      for (int cl = 0; cl < 3; cl++) part[mt][sb][cl] = 0.f;

  #pragma unroll
  for (int nt = 0; nt < 8; nt++){
    int col = wn + nt*8 + tg*2;
    float bv0 = bs[col], bv1 = bs[col + 1];
    float w[3][2];
    #pragma unroll
    for (int cl = 0; cl < 3; cl++){ w[cl][0] = w1s[cl*BN + col]; w[cl][1] = w1s[cl*BN + col + 1]; }
    #pragma unroll
    for (int mt = 0; mt < 2; mt++){
      float h00 = fmaxf(fmaf(c[mt][nt][0], WINV, bv0), 0.f);
      float h01 = fmaxf(fmaf(c[mt][nt][1], WINV, bv1), 0.f);
      float h10 = fmaxf(fmaf(c[mt][nt][2], WINV, bv0), 0.f);
      float h11 = fmaxf(fmaf(c[mt][nt][3], WINV, bv1), 0.f);
      #pragma unroll
      for (int cl = 0; cl < 3; cl++){
        part[mt][0][cl] = fmaf(h00, w[cl][0], fmaf(h01, w[cl][1], part[mt][0][cl]));
        part[mt][1][cl] = fmaf(h10, w[cl][0], fmaf(h11, w[cl][1], part[mt][1][cl]));
      }
    }
  }

  // reduce over the 4 tg-lanes sharing each row
  #pragma unroll
  for (int mt = 0; mt < 2; mt++)
    #pragma unroll
    for (int sb = 0; sb < 2; sb++)
      #pragma unroll
      for (int cl = 0; cl < 3; cl++){
        float v = part[mt][sb][cl];
        v += __shfl_xor_sync(0xffffffffu, v, 1);
        v += __shfl_xor_sync(0xffffffffu, v, 2);
        part[mt][sb][cl] = v;
      }
  if (tg == 0){
    #pragma unroll
    for (int mt = 0; mt < 2; mt++)
      #pragma unroll
      for (int sb = 0; sb < 2; sb++){
        int row = wm + mt*16 + g + sb*8;
        #pragma unroll
        for (int cl = 0; cl < 3; cl++)
          pps[(row*2 + (wid & 1))*3 + cl] = part[mt][sb][cl];
      }
  }
  __syncthreads();
  if (tid < BM){
    float4 o;
    o.x = pps[(tid*2)*3 + 0] + pps[(tid*2+1)*3 + 0];
    o.y = pps[(tid*2)*3 + 1] + pps[(tid*2+1)*3 + 1];
    o.z = pps[(tid*2)*3 + 2] + pps[(tid*2+1)*3 + 2];
    o.w = 0.f;
    g_pp[((size_t)z * M_ + m0 + tid) * NT + blockIdx.y] = o;
  }
  __syncthreads();

  // ---- in-kernel combine: last CTA of each (z, mtile) finalizes the 8 partials ----
  __shared__ int lastf;
  if (tid == 0){
    __threadfence();
    int old = atomicAdd(&g_tc[z*64 + blockIdx.x], 1);
    lastf = (old == NT - 1);
  }
  __syncthreads();
  if (lastf && tid < BM){
    __threadfence();
    const float4* pp = &g_pp[((size_t)z * M_ + m0 + tid) * NT];
    float s0 = 0.f, s1 = 0.f, s2 = 0.f;
    #pragma unroll
    for (int t = 0; t < NT; t++){ float4 v = pp[t]; s0 += v.x; s1 += v.y; s2 += v.z; }
    const float LOG2E = 1.4426950408889634f;
    int r = m0 + tid;
    if (z == 0){
      float mk = emask[r];
      g_ep[r] = make_float4(mk*s0*LOG2E, mk*s1*LOG2E, mk*s2*LOG2E, 0.f);
    } else {
      float mk = dmask[r];
      g_dp[r] = make_float4((mk*s0 + b1[0])*LOG2E, (mk*s1 + b1[1])*LOG2E, (mk*s2 + b1[2])*LOG2E, 0.f);
    }
  }
}

// ---------------- launch 3: grid NLL on packed int8 labels + fused final ----------------
__global__ __launch_bounds__(256) void grid_kernel(float* __restrict__ out)
{
  __shared__ float4 eps[1024];
  __shared__ float4 dps[16];
  __shared__ float redL[8];
  __shared__ int   redC[8];

  const int tid = threadIdx.x;
  const int b   = blockIdx.x >> 6;
  const int d0  = (blockIdx.x & 63) * 16;

  #pragma unroll
  for (int i = 0; i < 4; i++) eps[tid + 256*i] = g_ep[b*E_ + tid + 256*i];
  if (tid < 16) dps[tid] = g_dp[b*D_ + d0 + tid];
  __syncthreads();

  float accL = 0.f;
  int   accC = 0;
  const int e0 = tid * 4;

  for (int di = 0; di < 16; di++){
    float4 dp = dps[di];
    const uchar4* __restrict__ l4 = (const uchar4*)(g_lab8 + (((size_t)(b*D_ + d0 + di)) << 10));
    uchar4 lv = l4[tid];
    int li[4] = { (int)(signed char)lv.x, (int)(signed char)lv.y,
                  (int)(signed char)lv.z, (int)(signed char)lv.w };
    #pragma unroll
    for (int i = 0; i < 4; i++){
      float4 ep = eps[e0 + i];
      float l0 = dp.x + ep.x;
      float l1 = dp.y + ep.y;
      float l2 = dp.z + ep.z;
      float m12 = fmaxf(l1, l2), n12 = fminf(l1, l2);
      float m   = fmaxf(l0, m12), o1 = fminf(l0, m12);
      float sx = 1.0f + ex2f(o1 - m) + ex2f(n12 - m);
      float L = m + lg2f(sx);
      float ll = (li[i] == 0) ? l0 : ((li[i] == 1) ? l1 : l2);
      if (li[i] >= 0){ accL += L - ll; accC++; }
    }
  }

  #pragma unroll
  for (int o = 16; o; o >>= 1){
    accL += __shfl_xor_sync(0xffffffffu, accL, o);
    accC += __shfl_xor_sync(0xffffffffu, accC, o);
  }
  const int wid = tid >> 5, lane = tid & 31;
  if (lane == 0){ redL[wid] = accL; redC[wid] = accC; }
  __syncthreads();
  if (wid == 0 && lane < 8){
    float v = redL[lane];
    int   ct = redC[lane];
    #pragma unroll
    for (int o = 4; o; o >>= 1){
      v  += __shfl_xor_sync(0x000000ffu, v, o);
      ct += __shfl_xor_sync(0x000000ffu, ct, o);
    }
    if (lane == 0){
      atomicAdd(&g_sum, (double)v);
      atomicAdd(&g_cnt, (unsigned long long)ct);
      __threadfence();
      int done = atomicAdd(&g_done, 1);
      if (done == gridDim.x - 1){
        double denom = g_cnt ? (double)g_cnt : 1.0;
        out[0] = (float)(0.69314718055994530942 * g_sum / denom);
      }
    }
  }
}

// ---------------- launch ----------------
extern "C" void kernel_launch(void* const* d_in, const int* in_sizes, int n_in,
                              void* d_out, int out_size)
{
  (void)in_sizes; (void)n_in; (void)out_size;
  const float* enc   = (const float*)d_in[0];
  const float* dec   = (const float*)d_in[1];   // (1,B,D,F) == (B,D,F)
  const float* emask = (const float*)d_in[2];
  const float* dmask = (const float*)d_in[3];
  const float* W_e   = (const float*)d_in[4];
  const float* b_e   = (const float*)d_in[5];
  const float* W_d   = (const float*)d_in[6];
  const float* b_d   = (const float*)d_in[7];
  const float* W1    = (const float*)d_in[8];
  const float* b1    = (const float*)d_in[9];
  const int*   lab   = (const int*)d_in[10];
  float* out = (float*)d_out;

  static int smem_set = 0;
  if (!smem_set){
    cudaFuncSetAttribute(gemm_kernel, cudaFuncAttributeMaxDynamicSharedMemorySize, SM_TOTAL);
    smem_set = 1;
  }

  // launch 1: conversions + init + label packing (6144 + 512 blocks)
  cvt_all_kernel<<<XBLKS + NLBLK, 256>>>((const float4*)enc, (const float4*)dec,
                                         (const float4*)W_e, (const float4*)W_d, lab);

  // launch 2: GEMM + proj + combine (exact R12)
  dim3 gg(M_/BM, H_/BN, 2);   // (64, 8, 2)
  gemm_kernel<<<gg, 256, SM_TOTAL>>>(b_e, b_d, W1, emask, dmask, b1);

  // launch 3: grid NLL + final
  grid_kernel<<<512, 256>>>(out);
}

// round 16
// speedup vs baseline: 1.1778x; 1.0197x over previous
#include <cuda_runtime.h>
#include <cuda_bf16.h>
#include <cuda_fp16.h>
#include <cstdint>
#include <cstddef>

// Problem dims (fixed by the dataset)
#define B_ 8
#define E_ 1024
#define D_ 1024
#define F_ 768
#define H_ 1024
#define M_ 8192   // B*E == B*D rows

// GEMM tiling (fp8, f16 accum), R15 structure otherwise identical
#define BM 128
#define BN 128
#define BK 64
#define KITERS (F_ / BK)   // 12
#define NB 3
#define NT 8               // n-tiles (H/BN)
#define WSCALE 16.0f       // W pre-scale into e4m3 normal range
#define WINV   0.0625f

// smem: per buffer A 128x80B + B 128x80B
#define ROWW   20                         // words per row (64B data + 16B pad)
#define ATILE  (BM*ROWW*4)                // 10240 B
#define BUFSZ  (2*ATILE)                  // 20480 B (A + B)
#define SM_EXTRA (NB*BUFSZ)               // 61440
#define OF_W1  (SM_EXTRA)                 // 3*128 floats
#define OF_BS  (OF_W1 + 3*BN*4)
#define OF_PPS (OF_BS + BN*4)
#define SM_TOTAL (OF_PPS + BM*2*3*4)      // ~65 KB -> 2 CTAs/SM

#define NLAB (B_*D_*E_)                   // 8388608 labels
#define NLBLK 512                         // label-packing blocks appended to cvt launch
#define LPB (NLAB / NLBLK)                // 16384 labels per block

// ---------------- scratch (static device globals; no allocs) ----------------
__device__ uint8_t g_xe[(size_t)M_ * F_];    // e4m3
__device__ uint8_t g_xd[(size_t)M_ * F_];
__device__ uint8_t g_we[(size_t)H_ * F_];    // e4m3, scaled x16
__device__ uint8_t g_wd[(size_t)H_ * F_];
__device__ uint8_t g_lab8[NLAB];             // packed int8 labels
__device__ float4 g_pp[(size_t)2 * M_ * NT]; // per-(row, ntile) proj partials
__device__ float4 g_ep[M_];                  // e_proj * log2e (masked)
__device__ float4 g_dp[M_];                  // (d_proj*mask + b1) * log2e
__device__ double g_sum;
__device__ unsigned long long g_cnt;
__device__ int g_is32;                       // label dtype: 1 = int32, 0 = int64
__device__ int g_done;                       // last-block flag for fused final
__device__ int g_tc[2*64];                   // per-(z, mtile) completion counters

// ---------------- helpers ----------------
__device__ __forceinline__ float ex2f(float x){ float r; asm("ex2.approx.f32 %0, %1;" : "=f"(r) : "f"(x)); return r; }
__device__ __forceinline__ float lg2f(float x){ float r; asm("lg2.approx.f32 %0, %1;" : "=f"(r) : "f"(x)); return r; }

// fp8 mma with packed f16 accumulators (2 regs = 4 halves) — 2x rate vs f32 acc
__device__ __forceinline__ void mma_fp8_h(uint32_t c[2], const uint32_t a[4], const uint32_t b[2]){
  asm volatile(
    "mma.sync.aligned.m16n8k32.row.col.f16.e4m3.e4m3.f16 "
    "{%0,%1}, {%2,%3,%4,%5}, {%6,%7}, {%0,%1};\n"
    : "+r"(c[0]), "+r"(c[1])
    : "r"(a[0]), "r"(a[1]), "r"(a[2]), "r"(a[3]), "r"(b[0]), "r"(b[1]));
}

__device__ __forceinline__ void ldsm4(uint32_t r[4], uint32_t addr){
  asm volatile("ldmatrix.sync.aligned.m8n8.x4.shared.b16 {%0,%1,%2,%3}, [%4];"
    : "=r"(r[0]), "=r"(r[1]), "=r"(r[2]), "=r"(r[3]) : "r"(addr));
}

__device__ __forceinline__ void cp16(uint32_t smem_dst, const void* gsrc){
  asm volatile("cp.async.cg.shared.global [%0], [%1], 16;\n" :: "r"(smem_dst), "l"(gsrc));
}

// pack 4 fp32 -> 4 e4m3 bytes, round-to-nearest
__device__ __forceinline__ uint32_t pack4_e4m3(float4 v, float s){
  uint16_t lo, hi;
  asm("cvt.rn.satfinite.e4m3x2.f32 %0, %1, %2;" : "=h"(lo) : "f"(v.y * s), "f"(v.x * s));
  asm("cvt.rn.satfinite.e4m3x2.f32 %0, %1, %2;" : "=h"(hi) : "f"(v.w * s), "f"(v.z * s));
  return (uint32_t)lo | ((uint32_t)hi << 16);
}

// ---------------- launch 1: all conversions + init + label packing ----------------
#define NX4 ((M_ * F_) / 4)   // 1572864
#define NW4 ((H_ * F_) / 4)   // 196608
#define XBLKS ((NX4 + 255) / 256)   // 6144 cvt blocks; label blocks appended after
__global__ __launch_bounds__(256) void cvt_all_kernel(
    const float4* __restrict__ enc, const float4* __restrict__ dec,
    const float4* __restrict__ We,  const float4* __restrict__ Wd,
    const int* __restrict__ labw)
{
  const int bx = blockIdx.x;
  const int tid = threadIdx.x;

  // ---- appended label-packing blocks: int64/int32 labels -> int8 ----
  if (bx >= XBLKS){
    const int lidx = bx - XBLKS;              // 0..511
    // local dtype detection: int32 layout puts labels in odd words;
    // 256 samples of uniform{0,1,2} miss {1,2} w.p. (1/3)^256.
    __shared__ int sflag;
    if (tid == 0) sflag = 0;
    __syncthreads();
    {
      int v = labw[2*tid + 1];
      if (v == 1 || v == 2) sflag = 1;
    }
    __syncthreads();
    const int is32 = sflag;
    const int base = lidx * LPB;
    const int4* __restrict__ src = (const int4*)labw;
    uint32_t* __restrict__ dstw = (uint32_t*)(g_lab8 + base);
    #pragma unroll 4
    for (int it = 0; it < 16; it++){
      int li = base + (it*256 + tid)*4;       // 4 labels per step
      uint32_t o;
      if (is32){
        int4 v = src[li >> 2];
        o = (uint32_t)(v.x & 0xff) | ((uint32_t)(v.y & 0xff) << 8) |
            ((uint32_t)(v.z & 0xff) << 16) | ((uint32_t)(v.w & 0xff) << 24);
      } else {
        int4 v0 = src[li >> 1];               // labels li, li+1 (low words .x, .z)
        int4 v1 = src[(li >> 1) + 1];         // labels li+2, li+3
        o = (uint32_t)(v0.x & 0xff) | ((uint32_t)(v0.z & 0xff) << 8) |
            ((uint32_t)(v1.x & 0xff) << 16) | ((uint32_t)(v1.z & 0xff) << 24);
      }
      dstw[(it*256 + tid)] = o;
    }
    return;
  }

  // ---- conversion blocks ----
  int i = bx * 256 + tid;
  if (i < NX4){
    ((uint32_t*)g_xe)[i] = pack4_e4m3(enc[i], 1.0f);
    ((uint32_t*)g_xd)[i] = pack4_e4m3(dec[i], 1.0f);
  }
  if (i < NW4){
    ((uint32_t*)g_we)[i] = pack4_e4m3(We[i], WSCALE);
    ((uint32_t*)g_wd)[i] = pack4_e4m3(Wd[i], WSCALE);
  }
  if (bx == 0){
    if (tid < 128) g_tc[tid] = 0;
    if (tid == 0){
      g_sum = 0.0;
      g_cnt = 0ull;
      g_done = 0;
    }
  }
}

// ---------------- launch 2: fused GEMM + 3-class proj + in-kernel combine ----------------
// Grid (64, 8, 2); z=0 enc, z=1 dec. 2 CTAs/SM, 3-stage cp.async pipeline.
__global__ void __launch_bounds__(256, 2) gemm_kernel(
    const float* __restrict__ be, const float* __restrict__ bd,
    const float* __restrict__ W1,
    const float* __restrict__ emask, const float* __restrict__ dmask,
    const float* __restrict__ b1)
{
  extern __shared__ char sraw[];
  float* w1s = (float*)(sraw + OF_W1);   // [3][BN]
  float* bs  = (float*)(sraw + OF_BS);   // [BN]
  float* pps = (float*)(sraw + OF_PPS);  // [BM][2][3]
  const uint32_t sbase = (uint32_t)__cvta_generic_to_shared(sraw);

  const int z  = blockIdx.z;
  const uint8_t* __restrict__ X = z ? g_xd : g_xe;
  const uint8_t* __restrict__ W = z ? g_wd : g_we;
  const int m0 = blockIdx.x * BM;
  const int n0 = blockIdx.y * BN;

  const int tid  = threadIdx.x;
  const int wid  = tid >> 5, lane = tid & 31;
  const int g    = lane >> 2, tg = lane & 3;
  const int wm   = (wid >> 1) * 32;   // 4 warps in m (32 rows each)
  const int wn   = (wid & 1)  * 64;   // 2 warps in n (64 cols each)

  // ldmatrix per-lane address bases (80B row stride)
  const int q  = lane >> 3, r8 = lane & 7;
  const int rowA = wm + (q & 1) * 8 + r8;        // + mt*16
  const int wA   = (q >> 1) * 4;                 // + kb
  const int rowB0 = wn + (q >> 1) * 8 + r8;      // + np*16
  const int wB   = (q & 1) * 4;                  // + kb

  uint32_t c[2][8][2];   // packed f16x2 accumulators
  #pragma unroll
  for (int mt = 0; mt < 2; mt++)
    #pragma unroll
    for (int nt = 0; nt < 8; nt++){ c[mt][nt][0] = 0u; c[mt][nt][1] = 0u; }

  // epilogue constants into smem up front (protected by first loop sync)
  if (tid < BN) bs[tid] = (z ? bd : be)[n0 + tid];
  const int off1 = z ? 0 : H_;
  for (int i = tid; i < 3*BN; i += 256)
    w1s[i] = W1[(i >> 7) * (2*H_) + off1 + n0 + (i & 127)];

  // ---- async tile loader: 2 cp16 for A, 2 for B per thread ----
  auto load_tiles = [&](int s, int k0){
    #pragma unroll
    for (int i = 0; i < 2; i++){            // A: 512 16B-chunks
      int r  = (tid + 256*i) >> 2, ck = (tid + 256*i) & 3;
      uint32_t dst = sbase + (uint32_t)(s*BUFSZ + (r*ROWW + ck*4) * 4);
      cp16(dst, X + (size_t)(m0 + r)*F_ + k0 + ck*16);
    }
    #pragma unroll
    for (int i = 0; i < 2; i++){            // B: 512 16B-chunks
      int r  = (tid + 256*i) >> 2, ck = (tid + 256*i) & 3;
      uint32_t dst = sbase + (uint32_t)(s*BUFSZ + ATILE + (r*ROWW + ck*4) * 4);
      cp16(dst, W + (size_t)(n0 + r)*F_ + k0 + ck*16);
    }
  };

  load_tiles(0, 0);  asm volatile("cp.async.commit_group;\n");
  load_tiles(1, BK); asm volatile("cp.async.commit_group;\n");

  int s = 0;
  for (int it = 0; it < KITERS; it++){
    if (it + 1 < KITERS) asm volatile("cp.async.wait_group 1;\n");
    else                 asm volatile("cp.async.wait_group 0;\n");
    __syncthreads();   // single barrier per iter: also frees buffer (it+2)%3

    const uint32_t sA = sbase + s*BUFSZ;
    const uint32_t sB = sA + ATILE;
    #pragma unroll
    for (int ks = 0; ks < 2; ks++){         // two K=32 steps per 64B row
      const int kb = ks * 8;
      uint32_t a[2][4], b[8][2];
      #pragma unroll
      for (int mt = 0; mt < 2; mt++)
        ldsm4(a[mt], sA + (uint32_t)(((rowA + mt*16)*ROWW + kb + wA) * 4));
      #pragma unroll
      for (int np = 0; np < 4; np++){       // nt pairs (2 nt per ldsm4)
        uint32_t bb[4];
        ldsm4(bb, sB + (uint32_t)(((rowB0 + np*16)*ROWW + kb + wB) * 4));
        b[np*2    ][0] = bb[0]; b[np*2    ][1] = bb[1];
        b[np*2 + 1][0] = bb[2]; b[np*2 + 1][1] = bb[3];
      }
      #pragma unroll
      for (int mt = 0; mt < 2; mt++)
        #pragma unroll
        for (int nt = 0; nt < 8; nt++)
          mma_fp8_h(c[mt][nt], a[mt], b[nt]);
    }

    if (it + 2 < KITERS){
      load_tiles((it + 2) % NB, (it + 2) * BK);
      asm volatile("cp.async.commit_group;\n");
    }
    s = (s + 1 == NB) ? 0 : s + 1;
  }
  __syncthreads();

  // ---- fused epilogue: unscale + bias + relu + 3-class projection partials ----
  float part[2][2][3];
  #pragma unroll
  for (int mt = 0; mt < 2; mt++)
    #pragma unroll
    for (int sb = 0; sb < 2; sb++)
      #pragma unroll
      for (int cl = 0; cl < 3; cl++) part[mt][sb][cl] = 0.f;

  #pragma unroll
  for (int nt = 0; nt < 8; nt++){
    int col = wn + nt*8 + tg*2;
    float bv0 = bs[col], bv1 = bs[col + 1];
    float w[3][2];
    #pragma unroll
    for (int cl = 0; cl < 3; cl++){ w[cl][0] = w1s[cl*BN + col]; w[cl][1] = w1s[cl*BN + col + 1]; }
    #pragma unroll
    for (int mt = 0; mt < 2; mt++){
      float2 p01 = __half22float2(*(const __half2*)&c[mt][nt][0]);  // row g,   cols col/col+1
      float2 p23 = __half22float2(*(const __half2*)&c[mt][nt][1]);  // row g+8, cols col/col+1
      float h00 = fmaxf(fmaf(p01.x, WINV, bv0), 0.f);
      float h01 = fmaxf(fmaf(p01.y, WINV, bv1), 0.f);
      float h10 = fmaxf(fmaf(p23.x, WINV, bv0), 0.f);
      float h11 = fmaxf(fmaf(p23.y, WINV, bv1), 0.f);
      #pragma unroll
      for (int cl = 0; cl < 3; cl++){
        part[mt][0][cl] = fmaf(h00, w[cl][0], fmaf(h01, w[cl][1], part[mt][0][cl]));
        part[mt][1][cl] = fmaf(h10, w[cl][0], fmaf(h11, w[cl][1], part[mt][1][cl]));
      }
    }
  }

  // reduce over the 4 tg-lanes sharing each row
  #pragma unroll
  for (int mt = 0; mt < 2; mt++)
    #pragma unroll
    for (int sb = 0; sb < 2; sb++)
      #pragma unroll
      for (int cl = 0; cl < 3; cl++){
        float v = part[mt][sb][cl];
        v += __shfl_xor_sync(0xffffffffu, v, 1);
        v += __shfl_xor_sync(0xffffffffu, v, 2);
        part[mt][sb][cl] = v;
      }
  if (tg == 0){
    #pragma unroll
    for (int mt = 0; mt < 2; mt++)
      #pragma unroll
      for (int sb = 0; sb < 2; sb++){
        int row = wm + mt*16 + g + sb*8;
        #pragma unroll
        for (int cl = 0; cl < 3; cl++)
          pps[(row*2 + (wid & 1))*3 + cl] = part[mt][sb][cl];
      }
  }
  __syncthreads();
  if (tid < BM){
    float4 o;
    o.x = pps[(tid*2)*3 + 0] + pps[(tid*2+1)*3 + 0];
    o.y = pps[(tid*2)*3 + 1] + pps[(tid*2+1)*3 + 1];
    o.z = pps[(tid*2)*3 + 2] + pps[(tid*2+1)*3 + 2];
    o.w = 0.f;
    g_pp[((size_t)z * M_ + m0 + tid) * NT + blockIdx.y] = o;
  }
  __syncthreads();

  // ---- in-kernel combine: last CTA of each (z, mtile) finalizes the 8 partials ----
  __shared__ int lastf;
  if (tid == 0){
    __threadfence();
    int old = atomicAdd(&g_tc[z*64 + blockIdx.x], 1);
    lastf = (old == NT - 1);
  }
  __syncthreads();
  if (lastf && tid < BM){
    __threadfence();
    const float4* pp = &g_pp[((size_t)z * M_ + m0 + tid) * NT];
    float s0 = 0.f, s1 = 0.f, s2 = 0.f;
    #pragma unroll
    for (int t = 0; t < NT; t++){ float4 v = pp[t]; s0 += v.x; s1 += v.y; s2 += v.z; }
    const float LOG2E = 1.4426950408889634f;
    int r = m0 + tid;
    if (z == 0){
      float mk = emask[r];
      g_ep[r] = make_float4(mk*s0*LOG2E, mk*s1*LOG2E, mk*s2*LOG2E, 0.f);
    } else {
      float mk = dmask[r];
      g_dp[r] = make_float4((mk*s0 + b1[0])*LOG2E, (mk*s1 + b1[1])*LOG2E, (mk*s2 + b1[2])*LOG2E, 0.f);
    }
  }
}

// ---------------- launch 3: grid NLL on packed int8 labels + fused final ----------------
__global__ __launch_bounds__(256) void grid_kernel(float* __restrict__ out)
{
  __shared__ float4 eps[1024];
  __shared__ float4 dps[16];
  __shared__ float redL[8];
  __shared__ int   redC[8];

  const int tid = threadIdx.x;
  const int b   = blockIdx.x >> 6;
  const int d0  = (blockIdx.x & 63) * 16;

  #pragma unroll
  for (int i = 0; i < 4; i++) eps[tid + 256*i] = g_ep[b*E_ + tid + 256*i];
  if (tid < 16) dps[tid] = g_dp[b*D_ + d0 + tid];
  __syncthreads();

  float accL = 0.f;
  int   accC = 0;
  const int e0 = tid * 4;

  for (int di = 0; di < 16; di++){
    float4 dp = dps[di];
    const uchar4* __restrict__ l4 = (const uchar4*)(g_lab8 + (((size_t)(b*D_ + d0 + di)) << 10));
    uchar4 lv = l4[tid];
    int li[4] = { (int)(signed char)lv.x, (int)(signed char)lv.y,
                  (int)(signed char)lv.z, (int)(signed char)lv.w };
    #pragma unroll
    for (int i = 0; i < 4; i++){
      float4 ep = eps[e0 + i];
      float l0 = dp.x + ep.x;
      float l1 = dp.y + ep.y;
      float l2 = dp.z + ep.z;
      float m12 = fmaxf(l1, l2), n12 = fminf(l1, l2);
      float m   = fmaxf(l0, m12), o1 = fminf(l0, m12);
      float sx = 1.0f + ex2f(o1 - m) + ex2f(n12 - m);
      float L = m + lg2f(sx);
      float ll = (li[i] == 0) ? l0 : ((li[i] == 1) ? l1 : l2);
      if (li[i] >= 0){ accL += L - ll; accC++; }
    }
  }

  #pragma unroll
  for (int o = 16; o; o >>= 1){
    accL += __shfl_xor_sync(0xffffffffu, accL, o);
    accC += __shfl_xor_sync(0xffffffffu, accC, o);
  }
  const int wid = tid >> 5, lane = tid & 31;
  if (lane == 0){ redL[wid] = accL; redC[wid] = accC; }
  __syncthreads();
  if (wid == 0 && lane < 8){
    float v = redL[lane];
    int   ct = redC[lane];
    #pragma unroll
    for (int o = 4; o; o >>= 1){
      v  += __shfl_xor_sync(0x000000ffu, v, o);
      ct += __shfl_xor_sync(0x000000ffu, ct, o);
    }
    if (lane == 0){
      atomicAdd(&g_sum, (double)v);
      atomicAdd(&g_cnt, (unsigned long long)ct);
      __threadfence();
      int done = atomicAdd(&g_done, 1);
      if (done == gridDim.x - 1){
        double denom = g_cnt ? (double)g_cnt : 1.0;
        out[0] = (float)(0.69314718055994530942 * g_sum / denom);
      }
    }
  }
}

// ---------------- launch ----------------
extern "C" void kernel_launch(void* const* d_in, const int* in_sizes, int n_in,
                              void* d_out, int out_size)
{
  (void)in_sizes; (void)n_in; (void)out_size;
  const float* enc   = (const float*)d_in[0];
  const float* dec   = (const float*)d_in[1];   // (1,B,D,F) == (B,D,F)
  const float* emask = (const float*)d_in[2];
  const float* dmask = (const float*)d_in[3];
  const float* W_e   = (const float*)d_in[4];
  const float* b_e   = (const float*)d_in[5];
  const float* W_d   = (const float*)d_in[6];
  const float* b_d   = (const float*)d_in[7];
  const float* W1    = (const float*)d_in[8];
  const float* b1    = (const float*)d_in[9];
  const int*   lab   = (const int*)d_in[10];
  float* out = (float*)d_out;

  static int smem_set = 0;
  if (!smem_set){
    cudaFuncSetAttribute(gemm_kernel, cudaFuncAttributeMaxDynamicSharedMemorySize, SM_TOTAL);
    smem_set = 1;
  }

  // launch 1: conversions + init + label packing (6144 + 512 blocks)
  cvt_all_kernel<<<XBLKS + NLBLK, 256>>>((const float4*)enc, (const float4*)dec,
                                         (const float4*)W_e, (const float4*)W_d, lab);

  // launch 2: GEMM + proj + combine (f16-accumulator fp8 mma)
  dim3 gg(M_/BM, H_/BN, 2);   // (64, 8, 2)
  gemm_kernel<<<gg, 256, SM_TOTAL>>>(b_e, b_d, W1, emask, dmask, b1);

  // launch 3: grid NLL + final
  grid_kernel<<<512, 256>>>(out);
}